// round 5
// baseline (speedup 1.0000x reference)
#include <cuda_runtime.h>
#include <math.h>

#define BZ 64       // batch
#define SQ 1024     // seq len
#define HD 512      // hidden
#define GT 2048     // 4*H
#define KD 512      // input size
#define NCTA 128    // persistent CTAs in recurrence

// Static device scratch (cudaMalloc banned)
__device__ float g_xW[(size_t)SQ * GT * BZ];   // [s][n][b]  (R2 proven layout)
__device__ float g_h[2][BZ * KD];              // [b][k], full fp32 state
__device__ unsigned g_flag[(SQ + 1) * NCTA];   // per-step per-CTA arrival flags

typedef unsigned long long ull;

// ---------------- f32x2 helpers (phase 1, proven in R2) --------------------
__device__ __forceinline__ ull pack2(float lo, float hi) {
    ull r; asm("mov.b64 %0, {%1, %2};" : "=l"(r) : "f"(lo), "f"(hi)); return r;
}
__device__ __forceinline__ void fma2(ull& d, ull a, ull b) {
    asm("fma.rn.f32x2 %0, %1, %2, %0;" : "+l"(d) : "l"(a), "l"(b));
}
__device__ __forceinline__ float2 unpack2(ull v) {
    float2 f; asm("mov.b64 {%0, %1}, %2;" : "=f"(f.x), "=f"(f.y) : "l"(v)); return f;
}
__device__ __forceinline__ float sigmoidf_(float v) { return 1.f / (1.f + __expf(-v)); }
__device__ __forceinline__ float tanh_fast(float v) {
    float r; asm("tanh.approx.f32 %0, %1;" : "=f"(r) : "f"(v)); return r;
}

// ---------------- tf32 split WITHOUT cvt: mask-based, hi exact-tf32 --------
__device__ __forceinline__ float tf32_hi(float v) {
    return __uint_as_float(__float_as_uint(v) & 0xFFFFE000u);
}
__device__ __forceinline__ void mma8(float* d, const unsigned* a, const unsigned* b) {
    asm volatile("mma.sync.aligned.m16n8k8.row.col.f32.tf32.tf32.f32 "
                 "{%0,%1,%2,%3}, {%4,%5,%6,%7}, {%8,%9}, {%0,%1,%2,%3};\n"
                 : "+f"(d[0]), "+f"(d[1]), "+f"(d[2]), "+f"(d[3])
                 : "r"(a[0]), "r"(a[1]), "r"(a[2]), "r"(a[3]), "r"(b[0]), "r"(b[1]));
}

// ---------------------------------------------------------------------------
// Init: zero h buffers + flags (runs every graph replay)
// ---------------------------------------------------------------------------
__global__ void init_kernel() {
    int i = blockIdx.x * blockDim.x + threadIdx.x;
    if (i < 2 * BZ * KD) ((float*)g_h)[i] = 0.f;
    if (i < (SQ + 1) * NCTA) g_flag[i] = 0u;
}

// ---------------------------------------------------------------------------
// Phase 1 (VERBATIM from R2 -- proven): xW[s][n][b] = x @ W + bias
// ---------------------------------------------------------------------------
__global__ __launch_bounds__(256) void xw_gemm(const float* __restrict__ x,
                                               const float* __restrict__ W,
                                               const float* __restrict__ bias) {
    __shared__ __align__(16) float sAT[32][68];
    __shared__ __align__(16) float sB[32][128];

    const int s  = blockIdx.y;
    const int n0 = blockIdx.x * 128;
    const int tid = threadIdx.x;
    const int tx = tid & 15;
    const int ty = tid >> 4;

    ull acc2[4][4] = {};

    for (int k0 = 0; k0 < KD; k0 += 32) {
        #pragma unroll
        for (int h = 0; h < 2; h++) {
            int b  = h * 32 + (tid >> 3);
            int cc = tid & 7;
            float4 v = *(const float4*)(x + ((size_t)b * SQ + s) * KD + k0 + cc * 4);
            sAT[cc * 4 + 0][b] = v.x;
            sAT[cc * 4 + 1][b] = v.y;
            sAT[cc * 4 + 2][b] = v.z;
            sAT[cc * 4 + 3][b] = v.w;
        }
        #pragma unroll
        for (int h = 0; h < 4; h++) {
            int kk = h * 8 + (tid >> 5);
            int nn = (tid & 31) * 4;
            *(float4*)&sB[kk][nn] = *(const float4*)(W + (size_t)(k0 + kk) * GT + n0 + nn);
        }
        __syncthreads();

        #pragma unroll 8
        for (int kk = 0; kk < 32; kk++) {
            float4 a4 = *(const float4*)&sAT[kk][ty * 4];
            ull a2[4];
            a2[0] = pack2(a4.x, a4.x);
            a2[1] = pack2(a4.y, a4.y);
            a2[2] = pack2(a4.z, a4.z);
            a2[3] = pack2(a4.w, a4.w);
            double2 bl = *(const double2*)&sB[kk][tx * 8];
            double2 bh = *(const double2*)&sB[kk][tx * 8 + 4];
            ull bp[4];
            bp[0] = __double_as_longlong(bl.x);
            bp[1] = __double_as_longlong(bl.y);
            bp[2] = __double_as_longlong(bh.x);
            bp[3] = __double_as_longlong(bh.y);
            #pragma unroll
            for (int i = 0; i < 4; i++)
                #pragma unroll
                for (int p = 0; p < 4; p++)
                    fma2(acc2[i][p], a2[i], bp[p]);
        }
        __syncthreads();
    }

    float acc[4][8];
    #pragma unroll
    for (int i = 0; i < 4; i++)
        #pragma unroll
        for (int p = 0; p < 4; p++) {
            float2 f = unpack2(acc2[i][p]);
            acc[i][2 * p]     = f.x;
            acc[i][2 * p + 1] = f.y;
        }
    #pragma unroll
    for (int j = 0; j < 8; j++) {
        int n = n0 + tx * 8 + j;
        float bs = __ldg(bias + j + n0 + tx * 8);
        float4 o = make_float4(acc[0][j] + bs, acc[1][j] + bs,
                               acc[2][j] + bs, acc[3][j] + bs);
        *(float4*)(g_xW + ((size_t)s * GT + n) * BZ + ty * 4) = o;
    }
}

// ---------------------------------------------------------------------------
// Phase 2: persistent recurrence, tf32 mma with mask-split hi/lo (4 terms).
// Interleaved smem: per 8-k block, 16 floats (hi[q],lo[q],hi[q+4],lo[q+4])
// at offset q*4 + half*2 -> A frag = 2x LDS.128, B frag = 1x LDS.128.
// ---------------------------------------------------------------------------
#define ASTR 272    // hA row stride (floats)
#define BSTR 1040   // hU row stride (floats)

__global__ __launch_bounds__(256, 1) void lstm_rec(const float* __restrict__ U,
                                                   float* __restrict__ out, int has_hc) {
    extern __shared__ float sm[];
    float* hA = sm;                       // [2][64][ASTR] double-buffered h chunk
    float* hU = hA + 2 * 64 * ASTR;       // [16][BSTR]    resident U (full K)
    float* sg = hU + 16 * BSTR;           // [64][17]      gate staging

    const int tid = threadIdx.x;
    const int hc0 = blockIdx.x * 4;
    const int w = tid >> 5, lane = tid & 31;
    const int r = lane >> 2, cq = lane & 3;
    const int m0 = (w & 3) * 16;          // warp batch base
    const int col0 = (w >> 2) * 8;        // warp gate-col base

    const int eb = tid & 63;              // elementwise: batch (R2 proven map)
    const int jl = tid >> 6;              // elementwise: local h-col
    const int j = hc0 + jl;

    // Build resident interleaved U (hi,lo) from raw U, mask split
    for (int idx = tid; idx < 16 * KD; idx += 256) {
        int col = idx >> 9, k = idx & (KD - 1);
        int gc = (col >> 2) * HD + hc0 + (col & 3);
        float u = __ldg(U + (size_t)k * GT + gc);
        float hi = tf32_hi(u);
        float lo = u - hi;
        int off = (k >> 3) * 16 + (k & 3) * 4 + ((k >> 2) & 1) * 2;
        *(float2*)(hU + col * BSTR + off) = make_float2(hi, lo);
    }
    float c_reg = 0.f;

    float* out_hs = out;                               // [B][S][H]
    float* out_ht = out + (size_t)BZ * SQ * HD;
    float* out_ct = out_ht + (size_t)BZ * HD;

    __syncthreads();

    for (int t = 0; t < SQ; t++) {
        if (t > 0) {
            if (tid < NCTA) {
                volatile const unsigned* f = &g_flag[(size_t)t * NCTA + tid];
                while (*f == 0u) { }
            }
            __syncthreads();
            __threadfence();
        }

        const float* hsrc = g_h[t & 1];

        // prefetch chunk 0 (L2-coherent) + this thread's xW terms
        float4 v[8];
        #pragma unroll
        for (int i = 0; i < 8; i++) {
            int idx = i * 256 + tid;
            int b = idx >> 5, kf4 = idx & 31;
            v[i] = __ldcg((const float4*)(hsrc + b * KD + kf4 * 4));
        }
        float xwv[4];
        #pragma unroll
        for (int g = 0; g < 4; g++)
            xwv[g] = __ldcs(g_xW + ((size_t)t * GT + g * HD + j) * BZ + eb);

        float acc[4] = {0.f, 0.f, 0.f, 0.f};

        #pragma unroll
        for (int c = 0; c < 4; c++) {
            float* hAd = hA + (c & 1) * 64 * ASTR;
            // split + store chunk c (mask split, interleaved layout)
            #pragma unroll
            for (int i = 0; i < 8; i++) {
                int idx = i * 256 + tid;
                int b = idx >> 5, kf4 = idx & 31;
                int base = (kf4 >> 1) * 16 + (kf4 & 1) * 2;
                float* dst = hAd + b * ASTR + base;
                float hx, lx;
                hx = tf32_hi(v[i].x); lx = v[i].x - hx; *(float2*)(dst +  0) = make_float2(hx, lx);
                hx = tf32_hi(v[i].y); lx = v[i].y - hx; *(float2*)(dst +  4) = make_float2(hx, lx);
                hx = tf32_hi(v[i].z); lx = v[i].z - hx; *(float2*)(dst +  8) = make_float2(hx, lx);
                hx = tf32_hi(v[i].w); lx = v[i].w - hx; *(float2*)(dst + 12) = make_float2(hx, lx);
            }
            __syncthreads();
            if (c < 3) {       // prefetch next chunk (overlaps MMA)
                #pragma unroll
                for (int i = 0; i < 8; i++) {
                    int idx = i * 256 + tid;
                    int b = idx >> 5, kf4 = idx & 31;
                    v[i] = __ldcg((const float4*)(hsrc + b * KD + (c + 1) * 128 + kf4 * 4));
                }
            }
            // MMA over chunk c: 16 k-tiles of 8, 4 split terms
            const float* arow0 = hAd + (m0 + r) * ASTR + cq * 4;
            const float* arow1 = hAd + (m0 + r + 8) * ASTR + cq * 4;
            const float* brow  = hU + (col0 + r) * BSTR + c * 256 + cq * 4;
            #pragma unroll
            for (int kk = 0; kk < 16; kk++) {
                float4 A0 = *(const float4*)(arow0 + kk * 16);
                float4 A1 = *(const float4*)(arow1 + kk * 16);
                float4 Bv = *(const float4*)(brow  + kk * 16);
                unsigned ahi[4] = {__float_as_uint(A0.x), __float_as_uint(A1.x),
                                   __float_as_uint(A0.z), __float_as_uint(A1.z)};
                unsigned alo[4] = {__float_as_uint(A0.y), __float_as_uint(A1.y),
                                   __float_as_uint(A0.w), __float_as_uint(A1.w)};
                unsigned bhi[2] = {__float_as_uint(Bv.x), __float_as_uint(Bv.z)};
                unsigned blo[2] = {__float_as_uint(Bv.y), __float_as_uint(Bv.w)};
                mma8(acc, ahi, bhi);
                mma8(acc, alo, bhi);
                mma8(acc, ahi, blo);
                mma8(acc, alo, blo);
            }
            __syncthreads();   // before next chunk overwrites hAd parity buffer
        }

        // C frag -> sg[b][col]
        {
            int row0 = m0 + r, colb = col0 + cq * 2;
            sg[row0 * 17 + colb]           = acc[0];
            sg[row0 * 17 + colb + 1]       = acc[1];
            sg[(row0 + 8) * 17 + colb]     = acc[2];
            sg[(row0 + 8) * 17 + colb + 1] = acc[3];
        }
        __syncthreads();

        float gate[4];
        #pragma unroll
        for (int g = 0; g < 4; g++)
            gate[g] = xwv[g] + sg[eb * 17 + g * 4 + jl];

        float ig = sigmoidf_(gate[0]);
        float fg = sigmoidf_(gate[1]);
        float gg = tanh_fast(gate[2]);
        float og = sigmoidf_(gate[3]);
        c_reg = fg * c_reg + ig * gg;
        float hv = og * tanh_fast(c_reg);

        // publish full-precision h, fence, arrive
        g_h[(t + 1) & 1][eb * KD + j] = hv;
        __threadfence();
        __syncthreads();
        if (tid == 0) atomicExch(&g_flag[(size_t)(t + 1) * NCTA + blockIdx.x], 1u);

        // off-critical-path outputs
        out_hs[((size_t)eb * SQ + t) * HD + j] = hv;
        if (has_hc && t == SQ - 1) {
            out_ht[(size_t)eb * HD + j] = hv;
            out_ct[(size_t)eb * HD + j] = c_reg;
        }
    }
}

// ---------------------------------------------------------------------------
extern "C" void kernel_launch(void* const* d_in, const int* in_sizes, int n_in,
                              void* d_out, int out_size) {
    const float* x    = (const float*)d_in[0];
    const float* W    = (const float*)d_in[1];
    const float* U    = (const float*)d_in[2];
    const float* bias = (const float*)d_in[3];
    float* out = (float*)d_out;

    const int smem2 = (2 * 64 * ASTR + 16 * BSTR + 64 * 17) * (int)sizeof(float); // 210,176 B
    cudaFuncSetAttribute(lstm_rec, cudaFuncAttributeMaxDynamicSharedMemorySize, smem2);

    int has_hc = (out_size >= (int)((size_t)BZ * SQ * HD + 2 * BZ * HD)) ? 1 : 0;

    init_kernel<<<((SQ + 1) * NCTA + 255) / 256, 256>>>();
    xw_gemm<<<dim3(GT / 128, SQ), 256>>>(x, W, bias);
    lstm_rec<<<NCTA, 256, smem2>>>(U, out, has_hc);
}

// round 7
// speedup vs baseline: 2.1061x; 2.1061x over previous
#include <cuda_runtime.h>
#include <math.h>

#define BZ 64       // batch
#define SQ 1024     // seq len
#define HD 512      // hidden
#define GT 2048     // 4*H
#define KD 512      // input size
#define NCTA 128    // persistent CTAs in recurrence

// Static device scratch (cudaMalloc banned)
__device__ float g_xW[(size_t)SQ * GT * BZ];   // [s][n][b]
__device__ float g_h[2][BZ * KD];              // [b][k], full fp32 state
__device__ unsigned g_flag[(SQ + 1) * NCTA];   // per-step per-CTA arrival flags

typedef unsigned long long ull;

// ---------------- f32x2 helpers (phase 1, proven) --------------------------
__device__ __forceinline__ ull pack2(float lo, float hi) {
    ull r; asm("mov.b64 %0, {%1, %2};" : "=l"(r) : "f"(lo), "f"(hi)); return r;
}
__device__ __forceinline__ void fma2(ull& d, ull a, ull b) {
    asm("fma.rn.f32x2 %0, %1, %2, %0;" : "+l"(d) : "l"(a), "l"(b));
}
__device__ __forceinline__ float2 unpack2(ull v) {
    float2 f; asm("mov.b64 {%0, %1}, %2;" : "=f"(f.x), "=f"(f.y) : "l"(v)); return f;
}
__device__ __forceinline__ float sigmoidf_(float v) { return 1.f / (1.f + __expf(-v)); }
__device__ __forceinline__ float tanh_fast(float v) {
    float r; asm("tanh.approx.f32 %0, %1;" : "=f"(r) : "f"(v)); return r;
}

// ---------------- tf32 mask split (proven in R5) ---------------------------
__device__ __forceinline__ float tf32_hi(float v) {
    return __uint_as_float(__float_as_uint(v) & 0xFFFFE000u);
}
__device__ __forceinline__ void mma8(float* d, const unsigned* a, const unsigned* b) {
    asm volatile("mma.sync.aligned.m16n8k8.row.col.f32.tf32.tf32.f32 "
                 "{%0,%1,%2,%3}, {%4,%5,%6,%7}, {%8,%9}, {%0,%1,%2,%3};\n"
                 : "+f"(d[0]), "+f"(d[1]), "+f"(d[2]), "+f"(d[3])
                 : "r"(a[0]), "r"(a[1]), "r"(a[2]), "r"(a[3]), "r"(b[0]), "r"(b[1]));
}

// ---------------------------------------------------------------------------
// Phase 1 (R2 proven) + folded init: xW[s][n][b] = x @ W + bias
// blockIdx.y==0 blocks additionally zero g_h and g_flag (used only by lstm_rec,
// which launches after this kernel completes -- no race).
// ---------------------------------------------------------------------------
__global__ __launch_bounds__(256) void xw_gemm(const float* __restrict__ x,
                                               const float* __restrict__ W,
                                               const float* __restrict__ bias) {
    __shared__ __align__(16) float sAT[32][68];
    __shared__ __align__(16) float sB[32][128];

    const int s  = blockIdx.y;
    const int n0 = blockIdx.x * 128;
    const int tid = threadIdx.x;
    const int tx = tid & 15;
    const int ty = tid >> 4;

    if (blockIdx.y == 0) {              // folded init (16 blocks, 4096 threads)
        int gtid = blockIdx.x * 256 + tid;
        for (int i = gtid; i < 2 * BZ * KD; i += 4096) ((float*)g_h)[i] = 0.f;
        for (int i = gtid; i < (SQ + 1) * NCTA; i += 4096) g_flag[i] = 0u;
    }

    ull acc2[4][4] = {};

    for (int k0 = 0; k0 < KD; k0 += 32) {
        #pragma unroll
        for (int h = 0; h < 2; h++) {
            int b  = h * 32 + (tid >> 3);
            int cc = tid & 7;
            float4 v = *(const float4*)(x + ((size_t)b * SQ + s) * KD + k0 + cc * 4);
            sAT[cc * 4 + 0][b] = v.x;
            sAT[cc * 4 + 1][b] = v.y;
            sAT[cc * 4 + 2][b] = v.z;
            sAT[cc * 4 + 3][b] = v.w;
        }
        #pragma unroll
        for (int h = 0; h < 4; h++) {
            int kk = h * 8 + (tid >> 5);
            int nn = (tid & 31) * 4;
            *(float4*)&sB[kk][nn] = *(const float4*)(W + (size_t)(k0 + kk) * GT + n0 + nn);
        }
        __syncthreads();

        #pragma unroll 8
        for (int kk = 0; kk < 32; kk++) {
            float4 a4 = *(const float4*)&sAT[kk][ty * 4];
            ull a2[4];
            a2[0] = pack2(a4.x, a4.x);
            a2[1] = pack2(a4.y, a4.y);
            a2[2] = pack2(a4.z, a4.z);
            a2[3] = pack2(a4.w, a4.w);
            double2 bl = *(const double2*)&sB[kk][tx * 8];
            double2 bh = *(const double2*)&sB[kk][tx * 8 + 4];
            ull bp[4];
            bp[0] = __double_as_longlong(bl.x);
            bp[1] = __double_as_longlong(bl.y);
            bp[2] = __double_as_longlong(bh.x);
            bp[3] = __double_as_longlong(bh.y);
            #pragma unroll
            for (int i = 0; i < 4; i++)
                #pragma unroll
                for (int p = 0; p < 4; p++)
                    fma2(acc2[i][p], a2[i], bp[p]);
        }
        __syncthreads();
    }

    float acc[4][8];
    #pragma unroll
    for (int i = 0; i < 4; i++)
        #pragma unroll
        for (int p = 0; p < 4; p++) {
            float2 f = unpack2(acc2[i][p]);
            acc[i][2 * p]     = f.x;
            acc[i][2 * p + 1] = f.y;
        }
    #pragma unroll
    for (int j = 0; j < 8; j++) {
        int n = n0 + tx * 8 + j;
        float bs = __ldg(bias + n);
        float4 o = make_float4(acc[0][j] + bs, acc[1][j] + bs,
                               acc[2][j] + bs, acc[3][j] + bs);
        *(float4*)(g_xW + ((size_t)s * GT + n) * BZ + ty * 4) = o;
    }
}

// ---------------------------------------------------------------------------
// Phase 2: persistent recurrence, tf32 mma (mask split, 3 terms).
// Raw full-K h in smem (single stage + single sync); A-frags built inline
// (LDS.32 x4 + mask/sub, conflict-free). B = resident interleaved hi/lo U.
// ILP: 3 terms x 2-way k-split = 6 independent accumulators.
// ---------------------------------------------------------------------------
#define HSTR 516    // raw h row stride (floats)
#define BSTR 1040   // interleaved U row stride (floats)

__global__ __launch_bounds__(256, 1) void lstm_rec(const float* __restrict__ U,
                                                   float* __restrict__ out, int has_hc) {
    extern __shared__ float sm[];
    float* hs = sm;                       // [64][HSTR] raw fp32 h (full K)
    float* hU = hs + 64 * HSTR;           // [16][BSTR] resident U hi/lo interleaved
    float* sg = hU + 16 * BSTR;           // [64][17]   gate staging

    const int tid = threadIdx.x;
    const int hc0 = blockIdx.x * 4;
    const int w = tid >> 5, lane = tid & 31;
    const int r = lane >> 2, cq = lane & 3;
    const int m0 = (w & 3) * 16;          // warp batch base (4 x 2 warp grid)
    const int col0 = (w >> 2) * 8;        // warp gate-col base

    const int eb = tid & 63;              // elementwise: batch
    const int jl = tid >> 6;              // elementwise: local h-col
    const int j = hc0 + jl;

    // Build resident interleaved U (hi,lo): per 8-k block, 16 floats
    // (hi[q],lo[q],hi[q+4],lo[q+4]) at offset q*4 + half*2   (proven R5)
    for (int idx = tid; idx < 16 * KD; idx += 256) {
        int col = idx >> 9, k = idx & (KD - 1);
        int gc = (col >> 2) * HD + hc0 + (col & 3);
        float u = __ldg(U + (size_t)k * GT + gc);
        float hi = tf32_hi(u);
        float lo = u - hi;
        int off = (k >> 3) * 16 + (k & 3) * 4 + ((k >> 2) & 1) * 2;
        *(float2*)(hU + col * BSTR + off) = make_float2(hi, lo);
    }
    float c_reg = 0.f;

    float* out_hs = out;                               // [B][S][H]
    float* out_ht = out + (size_t)BZ * SQ * HD;
    float* out_ct = out_ht + (size_t)BZ * HD;

    __syncthreads();

    for (int t = 0; t < SQ; t++) {
        if (t > 0) {
            if (tid < NCTA) {
                volatile const unsigned* f = &g_flag[(size_t)t * NCTA + tid];
                while (*f == 0u) { }
            }
            __syncthreads();
            __threadfence();
        }

        // stage full raw h (64 x 512 = 128 KB) -- 32 coalesced float4/thread
        const float* hsrc = g_h[t & 1];
        #pragma unroll 8
        for (int i = 0; i < 32; i++) {
            int idx = i * 256 + tid;
            int b = idx >> 7, kf4 = idx & 127;
            float4 v = __ldcg((const float4*)(hsrc + b * KD + kf4 * 4));
            *(float4*)(hs + b * HSTR + kf4 * 4) = v;
        }
        // this thread's xW gate terms (independent)
        float xwv[4];
        #pragma unroll
        for (int g = 0; g < 4; g++)
            xwv[g] = __ldcs(g_xW + ((size_t)t * GT + g * HD + j) * BZ + eb);
        __syncthreads();

        // MMA: 64 k-tiles, 2-way k-split, 3 split terms -> 6 indep accumulators
        float aA0[4] = {}, aB0[4] = {}, aC0[4] = {};
        float aA1[4] = {}, aB1[4] = {}, aC1[4] = {};
        const float* arow0 = hs + (m0 + r) * HSTR;
        const float* arow1 = hs + (m0 + r + 8) * HSTR;
        const float* brow  = hU + (col0 + r) * BSTR;
        #pragma unroll 4
        for (int kk = 0; kk < 32; kk++) {
            // ---- k-half 0: tile kk ----
            {
                int kb = kk * 8;
                float f0 = arow0[kb + cq],     f1 = arow1[kb + cq];
                float f2 = arow0[kb + cq + 4], f3 = arow1[kb + cq + 4];
                float h0 = tf32_hi(f0), h1 = tf32_hi(f1), h2 = tf32_hi(f2), h3 = tf32_hi(f3);
                unsigned ahi[4] = {__float_as_uint(h0), __float_as_uint(h1),
                                   __float_as_uint(h2), __float_as_uint(h3)};
                unsigned alo[4] = {__float_as_uint(f0 - h0), __float_as_uint(f1 - h1),
                                   __float_as_uint(f2 - h2), __float_as_uint(f3 - h3)};
                float4 Bv = *(const float4*)(brow + kk * 16 + cq * 4);
                unsigned bhi[2] = {__float_as_uint(Bv.x), __float_as_uint(Bv.z)};
                unsigned blo[2] = {__float_as_uint(Bv.y), __float_as_uint(Bv.w)};
                mma8(aA0, ahi, bhi);
                mma8(aB0, alo, bhi);
                mma8(aC0, ahi, blo);
            }
            // ---- k-half 1: tile kk+32 ----
            {
                int kb = (kk + 32) * 8;
                float f0 = arow0[kb + cq],     f1 = arow1[kb + cq];
                float f2 = arow0[kb + cq + 4], f3 = arow1[kb + cq + 4];
                float h0 = tf32_hi(f0), h1 = tf32_hi(f1), h2 = tf32_hi(f2), h3 = tf32_hi(f3);
                unsigned ahi[4] = {__float_as_uint(h0), __float_as_uint(h1),
                                   __float_as_uint(h2), __float_as_uint(h3)};
                unsigned alo[4] = {__float_as_uint(f0 - h0), __float_as_uint(f1 - h1),
                                   __float_as_uint(f2 - h2), __float_as_uint(f3 - h3)};
                float4 Bv = *(const float4*)(brow + (kk + 32) * 16 + cq * 4);
                unsigned bhi[2] = {__float_as_uint(Bv.x), __float_as_uint(Bv.z)};
                unsigned blo[2] = {__float_as_uint(Bv.y), __float_as_uint(Bv.w)};
                mma8(aA1, ahi, bhi);
                mma8(aB1, alo, bhi);
                mma8(aC1, ahi, blo);
            }
        }

        // combine and stage C frag -> sg[b][col]
        {
            float c0 = aA0[0] + aB0[0] + aC0[0] + aA1[0] + aB1[0] + aC1[0];
            float c1 = aA0[1] + aB0[1] + aC0[1] + aA1[1] + aB1[1] + aC1[1];
            float c2 = aA0[2] + aB0[2] + aC0[2] + aA1[2] + aB1[2] + aC1[2];
            float c3 = aA0[3] + aB0[3] + aC0[3] + aA1[3] + aB1[3] + aC1[3];
            int row0 = m0 + r, colb = col0 + cq * 2;
            sg[row0 * 17 + colb]           = c0;
            sg[row0 * 17 + colb + 1]       = c1;
            sg[(row0 + 8) * 17 + colb]     = c2;
            sg[(row0 + 8) * 17 + colb + 1] = c3;
        }
        __syncthreads();

        float gate[4];
        #pragma unroll
        for (int g = 0; g < 4; g++)
            gate[g] = xwv[g] + sg[eb * 17 + g * 4 + jl];

        float ig = sigmoidf_(gate[0]);
        float fg = sigmoidf_(gate[1]);
        float gg = tanh_fast(gate[2]);
        float og = sigmoidf_(gate[3]);
        c_reg = fg * c_reg + ig * gg;
        float hv = og * tanh_fast(c_reg);

        // publish full-precision h, fence, arrive
        g_h[(t + 1) & 1][eb * KD + j] = hv;
        __threadfence();
        __syncthreads();
        if (tid == 0) atomicExch(&g_flag[(size_t)(t + 1) * NCTA + blockIdx.x], 1u);

        // off-critical-path outputs
        out_hs[((size_t)eb * SQ + t) * HD + j] = hv;
        if (has_hc && t == SQ - 1) {
            out_ht[(size_t)eb * HD + j] = hv;
            out_ct[(size_t)eb * HD + j] = c_reg;
        }
    }
}

// ---------------------------------------------------------------------------
extern "C" void kernel_launch(void* const* d_in, const int* in_sizes, int n_in,
                              void* d_out, int out_size) {
    const float* x    = (const float*)d_in[0];
    const float* W    = (const float*)d_in[1];
    const float* U    = (const float*)d_in[2];
    const float* bias = (const float*)d_in[3];
    float* out = (float*)d_out;

    const int smem2 = (64 * HSTR + 16 * BSTR + 64 * 17) * (int)sizeof(float); // 203,008 B
    cudaFuncSetAttribute(lstm_rec, cudaFuncAttributeMaxDynamicSharedMemorySize, smem2);

    int has_hc = (out_size >= (int)((size_t)BZ * SQ * HD + 2 * BZ * HD)) ? 1 : 0;

    xw_gemm<<<dim3(GT / 128, SQ), 256>>>(x, W, bias);
    lstm_rec<<<NCTA, 256, smem2>>>(U, out, has_hc);
}